// round 12
// baseline (speedup 1.0000x reference)
#include <cuda_runtime.h>
#include <cooperative_groups.h>
#include <math.h>

namespace cg = cooperative_groups;

#define Bc 64
#define Sc 2048
#define Hc 512
#define Kc 1024
#define SCC 8              // context CTAs per b == cluster size
#define SCHUNK (Sc/SCC)    // 256 rows per context CTA
#define CTHREADS 512
#define QB 16              // query rows per qproj CTA

// Scratch (no allocations allowed in kernel_launch)
__device__ float g_q[Bc*Hc];            // 128 KB
__device__ float g_scores[Bc*Sc];       // 512 KB

// tanh(x) = 1 - 2/(exp(2x)+1); __expf ~2ulp -> overall ~1e-6 error.
__device__ __forceinline__ float fast_tanhf(float x) {
    float e = __expf(2.0f * x);
    return 1.0f - __fdividef(2.0f, e + 1.0f);
}

#if defined(__CUDA_ARCH__) && (__CUDA_ARCH__ >= 900)
#define GRID_DEP_SYNC() cudaGridDependencySynchronize()
#else
#define GRID_DEP_SYNC()
#endif

// ---------------------------------------------------------------------------
// K1: q[b,h] = sum_e query[b,e] * W_q[h,e]
// grid (Hc/8, Bc/QB) = (64, 4), block 256 (8 warps).
// ---------------------------------------------------------------------------
__global__ void qproj_kernel(const float* __restrict__ query,
                             const float* __restrict__ Wq) {
    __shared__ float sq[QB][Hc];            // 32 KB
    const int t = threadIdx.x;
    const int warp = t >> 5, lane = t & 31;
    const int h  = blockIdx.x * 8 + warp;
    const int b0 = blockIdx.y * QB;

    const float4* wrow = (const float4*)(Wq + (size_t)h * Hc);
    float4 w0 = wrow[lane];
    float4 w1 = wrow[lane + 32];
    float4 w2 = wrow[lane + 64];
    float4 w3 = wrow[lane + 96];

    {
        const float4* qsrc = (const float4*)(query + (size_t)b0 * Hc);
        float4* qdst = (float4*)&sq[0][0];
#pragma unroll
        for (int j = 0; j < (QB*Hc/4)/256; j++)
            qdst[t + 256*j] = qsrc[t + 256*j];
    }
    __syncthreads();

#pragma unroll
    for (int bb = 0; bb < QB; bb++) {
        const float* qr = sq[bb];
        int e0 = lane*4, e1 = (lane+32)*4, e2 = (lane+64)*4, e3 = (lane+96)*4;
        float acc;
        acc = w0.x*qr[e0]   + w0.y*qr[e0+1] + w0.z*qr[e0+2] + w0.w*qr[e0+3];
        acc = fmaf(w1.x, qr[e1], acc); acc = fmaf(w1.y, qr[e1+1], acc);
        acc = fmaf(w1.z, qr[e1+2], acc); acc = fmaf(w1.w, qr[e1+3], acc);
        acc = fmaf(w2.x, qr[e2], acc); acc = fmaf(w2.y, qr[e2+1], acc);
        acc = fmaf(w2.z, qr[e2+2], acc); acc = fmaf(w2.w, qr[e2+3], acc);
        acc = fmaf(w3.x, qr[e3], acc); acc = fmaf(w3.y, qr[e3+1], acc);
        acc = fmaf(w3.z, qr[e3+2], acc); acc = fmaf(w3.w, qr[e3+3], acc);
#pragma unroll
        for (int o = 16; o; o >>= 1) acc += __shfl_xor_sync(0xffffffffu, acc, o);
        if (lane == 0) g_q[(b0 + bb)*Hc + h] = acc;
    }
}

// ---------------------------------------------------------------------------
// K2: scores[b,s] = sum_h tanh(q[b,h] + pk[b,s,h]) * v[h]
// block 256 (8 warps), warp handles 2 rows -> 16 rows/block, 8192 blocks.
// ---------------------------------------------------------------------------
__global__ void score_kernel(const float* __restrict__ pk,
                             const float* __restrict__ v) {
    __shared__ float sq[Hc];
    __shared__ float sv[Hc];
    const int t = threadIdx.x;
    const int row0 = blockIdx.x * 16;
    const int b = row0 >> 11;               // blocks don't straddle b
    sv[t]       = v[t];                     // input: no dependency
    sv[t + 256] = v[t + 256];
    GRID_DEP_SYNC();                        // wait for qproj's g_q
    sq[t]       = g_q[b*Hc + t];
    sq[t + 256] = g_q[b*Hc + t + 256];
    __syncthreads();

    const int warp = t >> 5, lane = t & 31;
    const int rowA = row0 + warp*2;
    const int rowB = rowA + 1;
    const float4* pA = (const float4*)(pk + (size_t)rowA * Hc);
    const float4* pB = (const float4*)(pk + (size_t)rowB * Hc);
    float accA = 0.0f, accB = 0.0f;
#pragma unroll
    for (int i = 0; i < 4; i++) {
        float4 a = pA[lane + 32*i];
        float4 c = pB[lane + 32*i];
        int e = (lane + 32*i) * 4;
        float q0 = sq[e], q1 = sq[e+1], q2 = sq[e+2], q3 = sq[e+3];
        float v0 = sv[e], v1 = sv[e+1], v2 = sv[e+2], v3 = sv[e+3];
        accA = fmaf(fast_tanhf(a.x + q0), v0, accA);
        accA = fmaf(fast_tanhf(a.y + q1), v1, accA);
        accA = fmaf(fast_tanhf(a.z + q2), v2, accA);
        accA = fmaf(fast_tanhf(a.w + q3), v3, accA);
        accB = fmaf(fast_tanhf(c.x + q0), v0, accB);
        accB = fmaf(fast_tanhf(c.y + q1), v1, accB);
        accB = fmaf(fast_tanhf(c.z + q2), v2, accB);
        accB = fmaf(fast_tanhf(c.w + q3), v3, accB);
    }
#pragma unroll
    for (int o = 16; o; o >>= 1) {
        accA += __shfl_xor_sync(0xffffffffu, accA, o);
        accB += __shfl_xor_sync(0xffffffffu, accB, o);
    }
    if (lane == 0) {
        g_scores[rowA] = accA;
        g_scores[rowB] = accB;
    }
}

// ---------------------------------------------------------------------------
// K3: cluster-fused softmax + context + reduction.
// grid (SCC, Bc) = (8, 64), 512 threads, cluster (8,1,1) = one cluster per b.
// Phase A (softmax, cooperative): each CTA owns 256 scores; local max/sum
//   partials exchanged via DSMEM scalars (2 cluster.syncs); each CTA
//   normalizes + writes its 256 alphas to d_out and keeps them in smem.
// Phase B (streaming): thread t owns k-slot (t&255), s-half (t>>8).
// Phase C (reduction): halves via smem, partial in spart[], cluster.sync,
//   8-rank DSMEM tree, rank-0 lanes write ctx. All orders fixed ->
//   deterministic.
// ---------------------------------------------------------------------------
__global__ void __cluster_dims__(SCC, 1, 1)
context_cluster_kernel(const float* __restrict__ eh,
                       const int* __restrict__ mask,
                       const float* __restrict__ g_sc,
                       float* __restrict__ alphas_out,
                       float* __restrict__ ctx_out) {
    __shared__ float  sa[SCHUNK];           // 1 KB  scores -> exp -> alphas
    __shared__ float4 shalf[Kc/4];          // 4 KB
    __shared__ float4 spart[Kc/4];          // 4 KB
    __shared__ float  s_red[16];
    __shared__ float  s_lmax;               // this CTA's local max
    __shared__ float  s_lsum;               // this CTA's local sum
    __shared__ float  s_bcast[2];
    cg::cluster_group cl = cg::this_cluster();
    const int c = blockIdx.x;               // == cluster rank
    const int b = blockIdx.y;
    const int t = threadIdx.x;
    const int warp = t >> 5, lane = t & 31;
    const int slot = t & 255;
    const int half = t >> 8;                // 0 or 1

    // pre-sync: mask is a kernel input
    int m = 1;
    if (t < SCHUNK) m = mask[b*Sc + c*SCHUNK + t];

    GRID_DEP_SYNC();                        // wait for score kernel's g_scores

    // ---- Phase A: cluster-cooperative masked softmax ----
    float lmax = -INFINITY;
    if (t < SCHUNK) {
        float x = g_sc[b*Sc + c*SCHUNK + t];
        if (m == 0) x = -INFINITY;
        sa[t] = x;
        lmax = x;
    }
#pragma unroll
    for (int o = 16; o; o >>= 1) lmax = fmaxf(lmax, __shfl_xor_sync(0xffffffffu, lmax, o));
    if (lane == 0) s_red[warp] = lmax;
    __syncthreads();
    if (t == 0) {
        float mx = s_red[0];
#pragma unroll
        for (int i = 1; i < 8; i++) mx = fmaxf(mx, s_red[i]);  // warps 8-15 inactive(-inf ok)
        for (int i = 8; i < 16; i++) mx = fmaxf(mx, s_red[i]);
        s_lmax = mx;
    }
    cl.sync();                              // all local maxima published

    if (warp == 0) {
        float v = -INFINITY;
        if (lane < SCC) v = *cl.map_shared_rank(&s_lmax, lane);
#pragma unroll
        for (int o = 4; o; o >>= 1) v = fmaxf(v, __shfl_xor_sync(0xffffffffu, v, o, 8));
        if (lane == 0) s_bcast[0] = v;
    }
    __syncthreads();
    const float gmax = s_bcast[0];

    float lsum = 0.0f;
    if (t < SCHUNK) {
        float e = __expf(sa[t] - gmax);
        sa[t] = e;
        lsum = e;
    }
#pragma unroll
    for (int o = 16; o; o >>= 1) lsum += __shfl_xor_sync(0xffffffffu, lsum, o);
    if (lane == 0) s_red[warp] = lsum;
    __syncthreads();
    if (t == 0) {
        float s = 0.0f;
#pragma unroll
        for (int i = 0; i < 16; i++) s += s_red[i];
        s_lsum = s;
    }
    cl.sync();                              // all local sums published

    if (warp == 0) {
        float v = 0.0f;
        if (lane < SCC) v = *cl.map_shared_rank(&s_lsum, lane);
#pragma unroll
        for (int o = 4; o; o >>= 1) v += __shfl_xor_sync(0xffffffffu, v, o, 8);
        if (lane == 0) s_bcast[1] = v;
    }
    __syncthreads();
    const float inv = 1.0f / s_bcast[1];
    if (t < SCHUNK) {
        float a = sa[t] * inv;
        sa[t] = a;
        alphas_out[b*Sc + c*SCHUNK + t] = a;
    }
    __syncthreads();

    // ---- Phase B: streaming partial over 256 rows (2 halves x 128) ----
    const float4* base =
        (const float4*)(eh + ((size_t)(b*Sc + c*SCHUNK + half*128)) * Kc) + slot;
    const float* sah = sa + half*128;
    float4 acc = make_float4(0.f, 0.f, 0.f, 0.f);
#pragma unroll 8
    for (int s = 0; s < 128; s++) {
        float a = sah[s];
        float4 vv = base[(size_t)s * (Kc/4)];
        acc.x = fmaf(a, vv.x, acc.x);
        acc.y = fmaf(a, vv.y, acc.y);
        acc.z = fmaf(a, vv.z, acc.z);
        acc.w = fmaf(a, vv.w, acc.w);
    }

    // ---- Phase C: combine halves, then 8-rank DSMEM reduction ----
    if (half == 1) shalf[slot] = acc;
    __syncthreads();
    if (half == 0) {
        float4 o = shalf[slot];
        acc.x += o.x; acc.y += o.y; acc.z += o.z; acc.w += o.w;
        spart[slot] = acc;
    }
    cl.sync();                              // all partials visible cluster-wide

    if (t < 256) {
        const int myslot = c*32 + (t >> 3); // this CTA's 32-slot stripe
        const int src    = t & 7;           // source rank
        const float4* rp = cl.map_shared_rank(spart, src);
        float4 v = rp[myslot];
#pragma unroll
        for (int o = 4; o; o >>= 1) {       // reduce within 8-lane segments
            v.x += __shfl_down_sync(0xffffffffu, v.x, o, 8);
            v.y += __shfl_down_sync(0xffffffffu, v.y, o, 8);
            v.z += __shfl_down_sync(0xffffffffu, v.z, o, 8);
            v.w += __shfl_down_sync(0xffffffffu, v.w, o, 8);
        }
        if (src == 0)
            ((float4*)ctx_out)[(size_t)b * (Kc/4) + myslot] = v;
    }
    cl.sync();                              // peers done reading our smem
}

// ---------------------------------------------------------------------------
template <typename K, typename... Args>
static inline void launch_pdl(K kernel, dim3 grid, dim3 block, Args... args) {
    cudaLaunchAttribute attr[1];
    attr[0].id = cudaLaunchAttributeProgrammaticStreamSerialization;
    attr[0].val.programmaticStreamSerializationAllowed = 1;
    cudaLaunchConfig_t cfg;
    cfg.gridDim = grid;
    cfg.blockDim = block;
    cfg.dynamicSmemBytes = 0;
    cfg.stream = 0;
    cfg.attrs = attr;
    cfg.numAttrs = 1;
    cudaLaunchKernelEx(&cfg, kernel, args...);
}

extern "C" void kernel_launch(void* const* d_in, const int* in_sizes, int n_in,
                              void* d_out, int out_size) {
    const float* query    = (const float*)d_in[0]; // (B,1,H)
    const float* proj_key = (const float*)d_in[1]; // (B,S,H)
    const float* enc      = (const float*)d_in[2]; // (B,S,K)
    const int*   mask     = (const int*)  d_in[3]; // (B,1,S)
    const float* Wq       = (const float*)d_in[4]; // (H,H)
    const float* v        = (const float*)d_in[5]; // (H,)

    float* ctx    = (float*)d_out;              // (B,1,K)
    float* alphas = (float*)d_out + Bc*Kc;      // (B,1,S)

    // device-symbol address for passing g_scores as a kernel arg
    float* scores_ptr = nullptr;
    cudaGetSymbolAddress((void**)&scores_ptr, g_scores);

    qproj_kernel<<<dim3(Hc/8, Bc/QB), 256>>>(query, Wq);
    launch_pdl(score_kernel,           dim3((Bc*Sc)/16), dim3(256), proj_key, v);
    launch_pdl(context_cluster_kernel, dim3(SCC, Bc),    dim3(CTHREADS), enc,
               mask, (const float*)scores_ptr, alphas, ctx);
}